// round 12
// baseline (speedup 1.0000x reference)
#include <cuda_runtime.h>
#include <cstdint>
#include <cstddef>

// ---------------------------------------------------------------------------
// DecoderTreeLSTM — round 11: cp.async double-buffered staging
//   * phase A: 4 slabs of 512 k-rows, cp.async prefetch of slab s+1 during
//     compute of slab s (staging latency fully hidden)
//   * level tasks: same pipeline with 4 slabs of 86 ph-rows
//   * NSTR=36 -> x reads are 4x LDS.128 broadcasts
// ---------------------------------------------------------------------------

#define NT      512
#define NMAX    1024
#define INDIM   2048
#define EMB     200
#define HID     1024
#define GC      5120          // 5*HID gate columns
#define OC      6144          // GC + HID
#define NCLS    151
#define NEMB    152
#define CH      32            // nodes per chunk
#define NSTR    36            // smem row stride (floats), 16B-aligned
#define BUFB_F  18432         // float offset of phase-A buffer B (512*36)
#define LVLB    3104          // float offset of level buffer B (86*36 -> pad)
#define SM_N    36864         // node cache (32 ints)
#define SM_PAR  36896         // parent cache (32 ints)
#define SM_T    36928         // task slot
#define SMEMB   147728        // bytes of dynamic smem

// ----- device scratch (static; no allocations anywhere) --------------------
__device__ float g_h[NMAX * HID];
__device__ float g_c[NMAX * HID];
__device__ float g_base[NMAX * OC];       // features @ W + biases
__device__ float g_E[NEMB * OC];          // embed @ W rows [2048:2248)
__device__ float g_part[3][NMAX * GC];    // per-level ph@W_iofuh partials
__device__ float g_zero[128];             // zero-filled (static init)
__device__ int   g_commit[NMAX];
__device__ int   g_order[NMAX];
__device__ int   g_lvloff[NMAX + 1];
__device__ int   g_nlev;
__device__ int   g_taskA;
__device__ int   g_taskL[NMAX];
__device__ volatile unsigned g_gen;
__device__ unsigned g_cnt;

// ----- helpers --------------------------------------------------------------
__device__ __forceinline__ float sigf(float x) {
    return 1.0f / (1.0f + expf(-x));
}

__device__ __forceinline__ float2 ffma2(float2 a, float2 b, float2 c) {
    unsigned long long ua = reinterpret_cast<unsigned long long&>(a);
    unsigned long long ub = reinterpret_cast<unsigned long long&>(b);
    unsigned long long uc = reinterpret_cast<unsigned long long&>(c);
    unsigned long long ud;
    asm("fma.rn.f32x2 %0, %1, %2, %3;" : "=l"(ud) : "l"(ua), "l"(ub), "l"(uc));
    return reinterpret_cast<float2&>(ud);
}

__device__ __forceinline__ void cpa4(uint32_t dst, const float* src) {
    asm volatile("cp.async.ca.shared.global [%0], [%1], 4;" :: "r"(dst), "l"(src));
}
#define CP_COMMIT() asm volatile("cp.async.commit_group;" ::: "memory")
#define CP_WAIT1()  asm volatile("cp.async.wait_group 1;" ::: "memory")
#define CP_WAIT0()  asm volatile("cp.async.wait_group 0;" ::: "memory")

// Sense-reversing grid barrier. Safe: grid == #SMs, 1 CTA/SM (regs+smem).
__device__ __forceinline__ void grid_sync() {
    __threadfence();
    __syncthreads();
    if (threadIdx.x == 0) {
        unsigned gen = g_gen;
        unsigned a = atomicAdd(&g_cnt, 1u);
        if (a == gridDim.x - 1u) {
            g_cnt = 0u;
            __threadfence();
            g_gen = gen + 1u;
        } else {
            while (g_gen == gen) { __nanosleep(32); }
        }
    }
    __syncthreads();
}

// One k-step: 4x LDS.128 broadcast of x (16 nodes), 32 FFMA2 into 8x4 accs.
__device__ __forceinline__ void stepk(const float4 w, const float* __restrict__ xrow,
                                      float2 acc[8][4])
{
    float2 wd0 = make_float2(w.x, w.x);
    float2 wd1 = make_float2(w.y, w.y);
    float2 wd2 = make_float2(w.z, w.z);
    float2 wd3 = make_float2(w.w, w.w);
    const float4* xr = reinterpret_cast<const float4*>(xrow);
    float4 a = xr[0], b = xr[1], c = xr[2], d = xr[3];
    float2 xp[8] = { {a.x,a.y},{a.z,a.w},{b.x,b.y},{b.z,b.w},
                     {c.x,c.y},{c.z,c.w},{d.x,d.y},{d.z,d.w} };
#pragma unroll
    for (int p = 0; p < 8; ++p) {
        acc[p][0] = ffma2(xp[p], wd0, acc[p][0]);
        acc[p][1] = ffma2(xp[p], wd1, acc[p][1]);
        acc[p][2] = ffma2(xp[p], wd2, acc[p][2]);
        acc[p][3] = ffma2(xp[p], wd3, acc[p][3]);
    }
}

// Pipelined rank-1 update over absolute W rows [ka, kb); x rows relative to
// staged slice start krel0; xbase pre-offset by node group.
__device__ __forceinline__ void pass_accum2(
    const float* __restrict__ Wb, int stride,
    const float* __restrict__ xbase, int krel0,
    int ka, int kb,
    float2 acc[8][4])
{
    const int nk = kb - ka;
    const float* wl = Wb + (size_t)ka * stride;
    const float* xc = xbase + (size_t)(ka - krel0) * NSTR;
    const int kq = nk & ~3;

    if (kq) {
        float4 w0 = *reinterpret_cast<const float4*>(wl);
        float4 w1 = *reinterpret_cast<const float4*>(wl + stride);
        float4 w2 = *reinterpret_cast<const float4*>(wl + 2 * stride);
        float4 w3 = *reinterpret_cast<const float4*>(wl + 3 * stride);
        wl += (size_t)4 * stride;
        for (int b = 4; b < kq; b += 4) {
            stepk(w0, xc, acc); w0 = *reinterpret_cast<const float4*>(wl);              xc += NSTR;
            stepk(w1, xc, acc); w1 = *reinterpret_cast<const float4*>(wl + stride);     xc += NSTR;
            stepk(w2, xc, acc); w2 = *reinterpret_cast<const float4*>(wl + 2 * stride); xc += NSTR;
            stepk(w3, xc, acc); w3 = *reinterpret_cast<const float4*>(wl + 3 * stride); xc += NSTR;
            wl += (size_t)4 * stride;
        }
        stepk(w0, xc, acc); xc += NSTR;
        stepk(w1, xc, acc); xc += NSTR;
        stepk(w2, xc, acc); xc += NSTR;
        stepk(w3, xc, acc); xc += NSTR;
    }
    for (int r = kq; r < nk; ++r) {
        float4 w = *reinterpret_cast<const float4*>(wl);
        wl += stride;
        stepk(w, xc, acc);
        xc += NSTR;
    }
}

// ----- the persistent kernel -------------------------------------------------
__global__ void __launch_bounds__(NT, 1)
tree_lstm_kernel(const float* __restrict__ features,
                 const int*   __restrict__ parent,
                 const int*   __restrict__ bsz_ptr,
                 const float* __restrict__ W_px,   const float* __restrict__ b_px,
                 const float* __restrict__ W_iofux,const float* __restrict__ b_iofux,
                 const float* __restrict__ W_iofuh,const float* __restrict__ b_iofuh,
                 const float* __restrict__ W_out,  const float* __restrict__ b_out,
                 const float* __restrict__ embed,
                 float* __restrict__ out,
                 int n, long long out_size)
{
    extern __shared__ float smf[];
    int* sN   = reinterpret_cast<int*>(smf) + SM_N;
    int* sPar = reinterpret_cast<int*>(smf) + SM_PAR;
    int* sT   = reinterpret_cast<int*>(smf) + SM_T;
    const uint32_t smem0 = (uint32_t)__cvta_generic_to_shared(smf);
    const int tid = threadIdx.x;
    const int B = bsz_ptr ? bsz_ptr[0] : 8;

    // ================= PREP (CTA 0) =================
    if (blockIdx.x == 0) {
        int* si  = reinterpret_cast<int*>(smf);
        int* anc = si;
        int* lv  = si + 1024;
        int* cnt = si + 2048;
        int* cur = si + 3072;

        if (tid == 0) g_taskA = 0;
        for (int i = tid; i < NMAX; i += NT) g_taskL[i] = 0;

        for (int i = tid; i < n; i += NT) {
            int p = parent[i];
            anc[i] = p;
            lv[i]  = (p >= 0) ? 1 : 0;
        }
        __syncthreads();

        for (int it = 0; it < 10; ++it) {     // pointer-doubling depth
            int ra[2], rl[2];
            int q = 0;
            for (int i = tid; i < n; i += NT, ++q) {
                int a = anc[i];
                rl[q] = (a >= 0) ? lv[a]  : 0;
                ra[q] = (a >= 0) ? anc[a] : -1;
            }
            __syncthreads();
            q = 0;
            for (int i = tid; i < n; i += NT, ++q) {
                lv[i]  += rl[q];
                anc[i]  = ra[q];
            }
            __syncthreads();
        }

        for (int i = tid; i < n; i += NT) cnt[i] = 0;
        if (tid == 0) si[4096] = 0;
        __syncthreads();
        int mx = 0;
        for (int i = tid; i < n; i += NT) {
            atomicAdd(&cnt[lv[i]], 1);
            if (lv[i] > mx) mx = lv[i];
        }
        atomicMax(&si[4096], mx);
        __syncthreads();
        int nlev = si[4096] + 1;

        if (tid == 0) {
            int s0 = 0;
            for (int l = 0; l < nlev; ++l) { g_lvloff[l] = s0; cur[l] = s0; s0 += cnt[l]; }
            g_lvloff[nlev] = s0;
            g_nlev = nlev;
        }
        __syncthreads();
        for (int i = tid; i < n; i += NT) {
            int pos = atomicAdd(&cur[lv[i]], 1);
            g_order[pos] = i;
        }
    }
    grid_sync();

    const int colt = tid & 31;
    const int wid  = tid >> 5;
    const int ng   = wid & 1;          // node group (16 nodes)
    const int kq8  = wid >> 1;         // k-eighth (0..7)

    // ================= PHASE A (work-stealing) =================
    {
        const int chunksA = (n + CH - 1) / CH;
        const int ntF = chunksA * 48;
        const int ntA = ntF + 5 * 48;        // + embed-table tasks

        for (;;) {
            if (tid == 0) sT[0] = atomicAdd(&g_taskA, 1);
            __syncthreads();
            const int task = sT[0];
            if (task >= ntA) break;

            float2 acc[8][4];
#pragma unroll
            for (int p = 0; p < 8; ++p)
#pragma unroll
                for (int c = 0; c < 4; ++c) acc[p][c] = make_float2(0.f, 0.f);

            if (task < ntF) {
                // ---- features GEMM task: 4 slabs of 512 rows, cp.async DB ----
                const int chunk = task / 48;
                const int cb    = task % 48;
                const int base  = chunk * CH;

                if (tid < 32) {
                    int node = base + tid; if (node > n - 1) node = n - 1;
                    sN[tid] = node;
                }
                __syncthreads();

                const float* Wb;
                int stride;
                if (cb < 40) { stride = GC;  Wb = W_iofux + cb * 128 + colt * 4; }
                else         { stride = HID; Wb = W_px + (cb - 40) * 128 + colt * 4; }

                // issue slab 0
                {
                    uint32_t dstb = smem0 + tid * (NSTR * 4);
                    const float* srcb = features + tid;
#pragma unroll 8
                    for (int m = 0; m < 32; ++m)
                        cpa4(dstb + m * 4, srcb + (size_t)sN[m] * INDIM);
                    CP_COMMIT();
                }
#pragma unroll 1
                for (int s = 0; s < 4; ++s) {
                    if (s < 3) {   // issue slab s+1 into the other buffer
                        uint32_t dstb = smem0 + (((s + 1) & 1) ? BUFB_F * 4 : 0)
                                              + tid * (NSTR * 4);
                        const float* srcb = features + (s + 1) * 512 + tid;
#pragma unroll 8
                        for (int m = 0; m < 32; ++m)
                            cpa4(dstb + m * 4, srcb + (size_t)sN[m] * INDIM);
                        CP_COMMIT();
                        CP_WAIT1();
                    } else {
                        CP_WAIT0();
                    }
                    __syncthreads();
                    const float* bufp = smf + ((s & 1) ? BUFB_F : 0);
                    const int s0 = s * 512;
                    const int ka = s0 + kq8 * 64;
                    pass_accum2(Wb, stride, bufp + ng * 16, s0, ka, ka + 64, acc);
                    __syncthreads();
                }

                // reduce [8][32][128] (overlays buffers)
                float* red = smf;
#pragma unroll
                for (int p = 0; p < 8; ++p) {
                    float4 lo4 = make_float4(acc[p][0].x, acc[p][1].x, acc[p][2].x, acc[p][3].x);
                    float4 hi4 = make_float4(acc[p][0].y, acc[p][1].y, acc[p][2].y, acc[p][3].y);
                    int rowA = kq8 * 32 + ng * 16 + 2 * p;
                    *reinterpret_cast<float4*>(red + (size_t)rowA       * 128 + colt * 4) = lo4;
                    *reinterpret_cast<float4*>(red + (size_t)(rowA + 1) * 128 + colt * 4) = hi4;
                }
                __syncthreads();
                {
                    const int m  = tid >> 4;
                    const int c0 = (tid & 15) * 8;
                    int node = base + m; if (node > n - 1) node = n - 1;
                    int gcol = (cb < 40) ? (cb * 128 + c0) : (GC + (cb - 40) * 128 + c0);
                    float* dst = g_base + (size_t)node * OC + gcol;
#pragma unroll
                    for (int i = 0; i < 2; ++i) {
                        float4 s = make_float4(0.f, 0.f, 0.f, 0.f);
#pragma unroll
                        for (int q = 0; q < 8; ++q) {
                            float4 v = *reinterpret_cast<const float4*>(
                                red + (size_t)(q * 32 + m) * 128 + c0 + i * 4);
                            s.x += v.x; s.y += v.y; s.z += v.z; s.w += v.w;
                        }
                        float4 bb;
                        if (cb < 40) {
                            float4 b1 = *reinterpret_cast<const float4*>(b_iofux + gcol + i * 4);
                            float4 b2 = *reinterpret_cast<const float4*>(b_iofuh + gcol + i * 4);
                            bb = make_float4(b1.x + b2.x, b1.y + b2.y, b1.z + b2.z, b1.w + b2.w);
                        } else {
                            bb = *reinterpret_cast<const float4*>(b_px + (gcol - GC) + i * 4);
                        }
                        s.x += bb.x; s.y += bb.y; s.z += bb.z; s.w += bb.w;
                        *reinterpret_cast<float4*>(dst + i * 4) = s;
                    }
                }
            } else {
                // ---- embed-table GEMM task: K=200, single cp.async stage ----
                const int et    = task - ntF;
                const int chunk = et / 48;
                const int cb    = et % 48;
                const int base  = chunk * CH;

                if (tid < 32) {
                    int e = base + tid; if (e > NEMB - 1) e = NEMB - 1;
                    sN[tid] = e;
                }
                __syncthreads();

                if (tid < EMB) {
                    uint32_t dstb = smem0 + tid * (NSTR * 4);
                    const float* srcb = embed + tid;
#pragma unroll 8
                    for (int m = 0; m < 32; ++m)
                        cpa4(dstb + m * 4, srcb + (size_t)sN[m] * EMB);
                }
                CP_COMMIT();
                CP_WAIT0();
                __syncthreads();

                const float* Wb;
                int stride;
                if (cb < 40) { stride = GC;  Wb = W_iofux + (size_t)INDIM * GC + cb * 128 + colt * 4; }
                else         { stride = HID; Wb = W_px + (size_t)INDIM * HID + (cb - 40) * 128 + colt * 4; }

                int ka = (EMB * kq8) / 8;
                int kb = (EMB * (kq8 + 1)) / 8;
                pass_accum2(Wb, stride, smf + ng * 16, 0, ka, kb, acc);
                __syncthreads();

                float* red = smf;
#pragma unroll
                for (int p = 0; p < 8; ++p) {
                    float4 lo4 = make_float4(acc[p][0].x, acc[p][1].x, acc[p][2].x, acc[p][3].x);
                    float4 hi4 = make_float4(acc[p][0].y, acc[p][1].y, acc[p][2].y, acc[p][3].y);
                    int rowA = kq8 * 32 + ng * 16 + 2 * p;
                    *reinterpret_cast<float4*>(red + (size_t)rowA       * 128 + colt * 4) = lo4;
                    *reinterpret_cast<float4*>(red + (size_t)(rowA + 1) * 128 + colt * 4) = hi4;
                }
                __syncthreads();
                {
                    const int m  = tid >> 4;
                    const int c0 = (tid & 15) * 8;
                    int e = base + m; if (e > NEMB - 1) e = NEMB - 1;
                    int gcol = (cb < 40) ? (cb * 128 + c0) : (GC + (cb - 40) * 128 + c0);
                    float* dst = g_E + (size_t)e * OC + gcol;
#pragma unroll
                    for (int i = 0; i < 2; ++i) {
                        float4 s = make_float4(0.f, 0.f, 0.f, 0.f);
#pragma unroll
                        for (int q = 0; q < 8; ++q) {
                            float4 v = *reinterpret_cast<const float4*>(
                                red + (size_t)(q * 32 + m) * 128 + c0 + i * 4);
                            s.x += v.x; s.y += v.y; s.z += v.z; s.w += v.w;
                        }
                        *reinterpret_cast<float4*>(dst + i * 4) = s;
                    }
                }
            }
        }
    }
    grid_sync();

    const int nlev = g_nlev;

    // ================= LEVEL LOOP =================
    for (int lev = 0; lev < nlev; ++lev) {
        const int lo = g_lvloff[lev];
        const int hi = g_lvloff[lev + 1];
        const int W  = hi - lo;

        // ---------- stage B: ph @ W_iofuh (cp.async pipelined) ----------
        const int chunks = (W + CH - 1) / CH;
        const int ntL = chunks * 120;           // 40 col-blocks x 3 k-splits
        for (;;) {
            if (tid == 0) sT[0] = atomicAdd(&g_taskL[lev], 1);
            __syncthreads();
            const int task = sT[0];
            if (task >= ntL) break;

            const int t     = task % 120;
            const int chunk = task / 120;
            const int cb    = t % 40;
            const int ks    = t / 40;
            const int base  = lo + chunk * CH;
            const int r0 = (ks * HID) / 3;
            const int r1 = ((ks + 1) * HID) / 3;

            if (tid < 32) {
                int slot = base + tid; if (slot > hi - 1) slot = hi - 1;
                int node = g_order[slot];
                sN[tid] = node;
                sPar[tid] = parent[node];
            }
            __syncthreads();

            // issue slab 0
            {
                const int a = r0;
                for (int idx = tid; idx < 32 * 86; idx += NT) {
                    int m  = idx / 86;
                    int kk = idx - m * 86;
                    int k  = a + kk;
                    if (k < r1) {
                        int pp = sPar[m];
                        const float* src = (pp >= 0) ? (g_h + (size_t)pp * HID + k)
                                                     : (g_zero + kk);
                        cpa4(smem0 + (uint32_t)kk * (NSTR * 4) + m * 4, src);
                    }
                }
                CP_COMMIT();
            }

            float2 acc[8][4];
#pragma unroll
            for (int p = 0; p < 8; ++p)
#pragma unroll
                for (int c = 0; c < 4; ++c) acc[p][c] = make_float2(0.f, 0.f);

#pragma unroll 1
            for (int s = 0; s < 4; ++s) {
                if (s < 3) {
                    const int a2 = r0 + (s + 1) * 86;
                    uint32_t dstb = smem0 + (((s + 1) & 1) ? LVLB * 4 : 0);
                    for (int idx = tid; idx < 32 * 86; idx += NT) {
                        int m  = idx / 86;
                        int kk = idx - m * 86;
                        int k  = a2 + kk;
                        if (k < r1) {
                            int pp = sPar[m];
                            const float* src = (pp >= 0) ? (g_h + (size_t)pp * HID + k)
                                                         : (g_zero + kk);
                            cpa4(dstb + (uint32_t)kk * (NSTR * 4) + m * 4, src);
                        }
                    }
                    CP_COMMIT();
                    CP_WAIT1();
                } else {
                    CP_WAIT0();
                }
                __syncthreads();
                const int a = r0 + s * 86;
                int b = a + 86; if (b > r1) b = r1;
                const int len = b - a;
                if (len > 0) {
                    const int ka = a + (len * kq8) / 8;
                    const int kb = a + (len * (kq8 + 1)) / 8;
                    const float* bufp = smf + ((s & 1) ? LVLB : 0);
                    pass_accum2(W_iofuh + cb * 128 + colt * 4, GC,
                                bufp + ng * 16, a, ka, kb, acc);
                }
                __syncthreads();
            }

            float* red = smf;
#pragma unroll
            for (int p = 0; p < 8; ++p) {
                float4 lo4 = make_float4(acc[p][0].x, acc[p][1].x, acc[p][2].x, acc[p][3].x);
                float4 hi4 = make_float4(acc[p][0].y, acc[p][1].y, acc[p][2].y, acc[p][3].y);
                int rowA = kq8 * 32 + ng * 16 + 2 * p;
                *reinterpret_cast<float4*>(red + (size_t)rowA       * 128 + colt * 4) = lo4;
                *reinterpret_cast<float4*>(red + (size_t)(rowA + 1) * 128 + colt * 4) = hi4;
            }
            __syncthreads();
            {
                const int m  = tid >> 4;
                const int c0 = (tid & 15) * 8;
                int slot = base + m; if (slot > hi - 1) slot = hi - 1;
                int node = g_order[slot];
                int gcol = cb * 128 + c0;
                float* dst = g_part[ks] + (size_t)node * GC + gcol;
#pragma unroll
                for (int i = 0; i < 2; ++i) {
                    float4 s = make_float4(0.f, 0.f, 0.f, 0.f);
#pragma unroll
                    for (int q = 0; q < 8; ++q) {
                        float4 v = *reinterpret_cast<const float4*>(
                            red + (size_t)(q * 32 + m) * 128 + c0 + i * 4);
                        s.x += v.x; s.y += v.y; s.z += v.z; s.w += v.w;
                    }
                    *reinterpret_cast<float4*>(dst + i * 4) = s;
                }
            }
        }
        grid_sync();

        // ---------- stage CD: gates + output head, one CTA per node ----------
        for (int s = blockIdx.x; s < W; s += gridDim.x) {
            const int node = g_order[lo + s];
            const int par  = parent[node];
            const int cmIdx = (par >= 0) ? g_commit[par] : 0;
            const float* gb = g_base + (size_t)node * OC;
            const float* er = g_E + (size_t)cmIdx * OC;
            const float* p0 = g_part[0] + (size_t)node * GC;
            const float* p1 = g_part[1] + (size_t)node * GC;
            const float* p2 = g_part[2] + (size_t)node * GC;
            float* hb   = smf;              // h_final, 1024 floats
            float* part = smf + HID;        // 512 partials for W_out GEMV
            float* db   = smf + HID + 512;  // dist, 151 floats
            int*   cms  = reinterpret_cast<int*>(smf) + HID + 512 + 256;

            const int j = tid * 2;          // 512*2 == 1024
#define GGATE(OFF) make_float2( \
            gb[(OFF) + j]     + er[(OFF) + j]     + p0[(OFF) + j]     + p1[(OFF) + j]     + p2[(OFF) + j], \
            gb[(OFF) + j + 1] + er[(OFF) + j + 1] + p0[(OFF) + j + 1] + p1[(OFF) + j + 1] + p2[(OFF) + j + 1])
            float2 ig2 = GGATE(0);
            float2 og2 = GGATE(HID);
            float2 fg2 = GGATE(2 * HID);
            float2 ug2 = GGATE(3 * HID);
            float2 rg2 = GGATE(4 * HID);
#undef GGATE
            float2 pj2 = make_float2(gb[GC + j]     + er[GC + j],
                                     gb[GC + j + 1] + er[GC + j + 1]);
            float2 pc2 = make_float2(0.f, 0.f);
            if (par >= 0)
                pc2 = *reinterpret_cast<const float2*>(g_c + (size_t)par * HID + j);

            float2 c2, hf2;
            {
                float iS, oS, fS, rS, cv, hv;
#define ELT(CC, HH, IG, OG, FG, UG, RG, PJ, PC)            \
                iS = sigf(IG); oS = sigf(OG); fS = sigf(FG); rS = sigf(RG); \
                cv = iS * tanhf(UG) + fS * (PC);           \
                hv = oS * tanhf(cv);                       \
                CC = cv; HH = rS * hv + (1.0f - rS) * (PJ);
                ELT(c2.x, hf2.x, ig2.x, og2.x, fg2.x, ug2.x, rg2.x, pj2.x, pc2.x)
                ELT(c2.y, hf2.y, ig2.y, og2.y, fg2.y, ug2.y, rg2.y, pj2.y, pc2.y)
#undef ELT
            }
            *reinterpret_cast<float2*>(g_c + (size_t)node * HID + j) = c2;
            *reinterpret_cast<float2*>(g_h + (size_t)node * HID + j) = hf2;
            *reinterpret_cast<float2*>(hb + j) = hf2;
            __syncthreads();

            // dist = h_final @ W_out + b_out ; 2-way k-split, 4 accumulators
            {
                const int c   = tid & 255;
                const int seg = tid >> 8;
                if (c < NCLS) {
                    const float* wc = W_out + c;
                    const int k0 = seg * 512;
                    float a0 = (seg == 0) ? b_out[c] : 0.0f;
                    float a1 = 0.f, a2 = 0.f, a3 = 0.f;
#pragma unroll 4
                    for (int k = k0; k < k0 + 512; k += 4) {
                        a0 = fmaf(hb[k],     wc[(size_t)(k)     * NCLS], a0);
                        a1 = fmaf(hb[k + 1], wc[(size_t)(k + 1) * NCLS], a1);
                        a2 = fmaf(hb[k + 2], wc[(size_t)(k + 2) * NCLS], a2);
                        a3 = fmaf(hb[k + 3], wc[(size_t)(k + 3) * NCLS], a3);
                    }
                    part[seg * 256 + c] = (a0 + a1) + (a2 + a3);
                }
            }
            __syncthreads();
            if (tid < NCLS) {
                float a = part[tid] + part[256 + tid];
                db[tid] = a;
                if (node >= B) {
                    size_t off = (size_t)(node - B) * NCLS + tid;
                    if (off < (size_t)out_size) out[off] = a;
                }
            }
            __syncthreads();

            // warp-parallel argmax over dist[1:], first-max semantics
            if (tid < 32) {
                float best = -3.4e38f; int bi = NCLS;
                for (int q = 1 + tid; q < NCLS; q += 32) {
                    float v = db[q];
                    if (v > best) { best = v; bi = q; }
                }
#pragma unroll
                for (int off = 16; off > 0; off >>= 1) {
                    float ov = __shfl_down_sync(0xffffffffu, best, off);
                    int   oi = __shfl_down_sync(0xffffffffu, bi, off);
                    if (ov > best || (ov == best && oi < bi)) { best = ov; bi = oi; }
                }
                if (tid == 0) { g_commit[node] = bi; cms[0] = bi; }
            }
            __syncthreads();
        }
        grid_sync();
    }

    // ================= commitments tail =================
    const int NBo = n - B;
    for (int jj = blockIdx.x * NT + tid; jj < n; jj += gridDim.x * NT) {
        size_t off = (size_t)NBo * NCLS + jj;
        if (off < (size_t)out_size) {
            float v = (jj < NBo) ? (float)g_commit[B + jj] : 0.0f;
            out[off] = v;
        }
    }
}

// ----- host launcher ----------------------------------------------------------
extern "C" void kernel_launch(void* const* d_in, const int* in_sizes, int n_in,
                              void* d_out, int out_size)
{
    const float* features = (const float*)d_in[0];
    const int*   parent   = (const int*)  d_in[1];

    const int* bptr = nullptr;
    int base = 2;
    if (n_in >= 12) { bptr = (const int*)d_in[2]; base = 3; }

    const float* W_px    = (const float*)d_in[base + 0];
    const float* b_px    = (const float*)d_in[base + 1];
    const float* W_iofux = (const float*)d_in[base + 2];
    const float* b_iofux = (const float*)d_in[base + 3];
    const float* W_iofuh = (const float*)d_in[base + 4];
    const float* b_iofuh = (const float*)d_in[base + 5];
    const float* W_out   = (const float*)d_in[base + 6];
    const float* b_out   = (const float*)d_in[base + 7];
    const float* embed   = (const float*)d_in[base + 8];

    int n = in_sizes[1];
    if (n > NMAX) n = NMAX;

    int dev = 0, sms = 0;
    cudaGetDevice(&dev);
    cudaDeviceGetAttribute(&sms, cudaDevAttrMultiProcessorCount, dev);
    if (sms <= 0) sms = 148;

    cudaFuncSetAttribute(tree_lstm_kernel,
                         cudaFuncAttributeMaxDynamicSharedMemorySize, SMEMB);

    tree_lstm_kernel<<<sms, NT, SMEMB>>>(
        features, parent, bptr,
        W_px, b_px, W_iofux, b_iofux, W_iofuh, b_iofuh,
        W_out, b_out, embed,
        (float*)d_out, n, (long long)out_size);
}